// round 1
// baseline (speedup 1.0000x reference)
#include <cuda_runtime.h>
#include <cuda_bf16.h>
#include <math.h>

// ---------------------------------------------------------------------------
// EncoderLayer: B=32, S=512, D=1024, H=16, dk=64, F=4096
// Round 0: fp32 baseline. GEMMs = tiled FFMA SGEMM; fused attention; fused LN.
// ---------------------------------------------------------------------------

#define B_  32
#define S_  512
#define D_  1024
#define H_  16
#define DK_ 64
#define F_  4096
#define M_  (B_ * S_)          // 16384 rows

// -------------------- scratch (device globals; no allocs) ------------------
__device__ float g_q   [M_ * D_];
__device__ float g_k   [M_ * D_];
__device__ float g_v   [M_ * D_];
__device__ float g_ctx [M_ * D_];
__device__ float g_attn[M_ * D_];
__device__ float g_out1[M_ * D_];
__device__ float g_ffn [M_ * D_];
__device__ float g_h   [M_ * F_];

// ---------------------------------------------------------------------------
// SGEMM: C[M,N] = act(A[M,K] @ Bmat[K,N] + bias[N])
// 128x128 block tile, 8x8 per thread, BK=8, 256 threads, double-buffered smem.
// ---------------------------------------------------------------------------
__device__ __forceinline__ float gelu_erf_f(float x) {
    return 0.5f * x * (1.0f + erff(x * 0.70710678118654752f));
}

template <int ACT>
__global__ __launch_bounds__(256) void sgemm_bias(
    const float* __restrict__ A, const float* __restrict__ Bm,
    const float* __restrict__ bias, float* __restrict__ C,
    int M, int N, int K)
{
    __shared__ float As[2][8][128];
    __shared__ float Bs[2][8][128];

    const int tid = threadIdx.x;
    const int bx = blockIdx.x, by = blockIdx.y;
    const int tx = tid & 15, ty = tid >> 4;

    const int arow = tid >> 1, acol = (tid & 1) << 2;
    const int brow = tid >> 5, bcol = (tid & 31) << 2;

    const float* Aptr = A + (by * 128 + arow) * K + acol;
    const float* Bptr = Bm + brow * N + bx * 128 + bcol;

    float acc[8][8];
    #pragma unroll
    for (int i = 0; i < 8; i++)
        #pragma unroll
        for (int j = 0; j < 8; j++) acc[i][j] = 0.f;

    // prologue: tile 0 -> buffer 0
    {
        float4 a4 = *(const float4*)Aptr;
        As[0][acol + 0][arow] = a4.x;
        As[0][acol + 1][arow] = a4.y;
        As[0][acol + 2][arow] = a4.z;
        As[0][acol + 3][arow] = a4.w;
        *(float4*)&Bs[0][brow][bcol] = *(const float4*)Bptr;
    }
    __syncthreads();

    const int nk = K >> 3;
    for (int kt = 0; kt < nk; ++kt) {
        const int cur = kt & 1;
        float4 a4, b4;
        const bool has = (kt + 1 < nk);
        if (has) {
            a4 = *(const float4*)(Aptr + (kt + 1) * 8);
            b4 = *(const float4*)(Bptr + (kt + 1) * 8 * N);
        }
        #pragma unroll
        for (int k = 0; k < 8; k++) {
            float ar[8], br[8];
            *(float4*)&ar[0] = *(const float4*)&As[cur][k][ty * 8];
            *(float4*)&ar[4] = *(const float4*)&As[cur][k][ty * 8 + 4];
            *(float4*)&br[0] = *(const float4*)&Bs[cur][k][tx * 8];
            *(float4*)&br[4] = *(const float4*)&Bs[cur][k][tx * 8 + 4];
            #pragma unroll
            for (int i = 0; i < 8; i++)
                #pragma unroll
                for (int j = 0; j < 8; j++)
                    acc[i][j] += ar[i] * br[j];
        }
        if (has) {
            const int nxt = cur ^ 1;
            As[nxt][acol + 0][arow] = a4.x;
            As[nxt][acol + 1][arow] = a4.y;
            As[nxt][acol + 2][arow] = a4.z;
            As[nxt][acol + 3][arow] = a4.w;
            *(float4*)&Bs[nxt][brow][bcol] = b4;
        }
        __syncthreads();
    }

    const int crow = by * 128 + ty * 8;
    const int ccol = bx * 128 + tx * 8;
    float bv[8];
    #pragma unroll
    for (int j = 0; j < 8; j++) bv[j] = bias[ccol + j];

    #pragma unroll
    for (int i = 0; i < 8; i++) {
        float* Crow = C + (size_t)(crow + i) * N + ccol;
        float o[8];
        #pragma unroll
        for (int j = 0; j < 8; j++) {
            float v = acc[i][j] + bv[j];
            if (ACT == 1) v = gelu_erf_f(v);
            o[j] = v;
        }
        *(float4*)&Crow[0] = *(float4*)&o[0];
        *(float4*)&Crow[4] = *(float4*)&o[4];
    }
}

// ---------------------------------------------------------------------------
// Fused attention: grid (S/64, H, B), 256 threads.
// smem: scores[64][516] + Qs[64][68] + KV tile[64][68]  = 166,912 bytes.
// ---------------------------------------------------------------------------
#define SC_STRIDE 516
#define QK_STRIDE 68

__global__ __launch_bounds__(256) void attention_kernel(
    const float* __restrict__ Q, const float* __restrict__ K,
    const float* __restrict__ V, const int* __restrict__ mask,
    const float* __restrict__ adj, float* __restrict__ ctx)
{
    extern __shared__ float smem[];
    float* sc = smem;                       // 64 * 516
    float* qs = sc + 64 * SC_STRIDE;        // 64 * 68
    float* kv = qs + 64 * QK_STRIDE;        // 64 * 68

    const int t  = threadIdx.x;
    const int qt = blockIdx.x, h = blockIdx.y, b = blockIdx.z;
    const int qbase = b * S_ + qt * 64;

    // load Q tile, pre-scaled by 1/sqrt(dk) = 0.125
    #pragma unroll
    for (int i = 0; i < 4; i++) {
        int lin = t + i * 256;
        int r = lin >> 4, c4 = (lin & 15) << 2;
        float4 qv = *(const float4*)&Q[(size_t)(qbase + r) * D_ + h * DK_ + c4];
        qv.x *= 0.125f; qv.y *= 0.125f; qv.z *= 0.125f; qv.w *= 0.125f;
        *(float4*)&qs[r * QK_STRIDE + c4] = qv;
    }

    const int qi  = t >> 2;
    const int kj0 = (t & 3) << 4;
    const int qg  = qt * 64 + qi;

    // ---- phase 1: scores = QK^T/8 + mask*(-1e9) + adj ----
    for (int kt = 0; kt < 8; ++kt) {
        __syncthreads();   // protect kv reuse (also orders qs stores on kt==0)
        #pragma unroll
        for (int i = 0; i < 4; i++) {
            int lin = t + i * 256;
            int r = lin >> 4, c4 = (lin & 15) << 2;
            float4 kk = *(const float4*)&K[(size_t)(b * S_ + kt * 64 + r) * D_ + h * DK_ + c4];
            kv[(c4 + 0) * QK_STRIDE + r] = kk.x;   // transposed: kv[d][kj]
            kv[(c4 + 1) * QK_STRIDE + r] = kk.y;
            kv[(c4 + 2) * QK_STRIDE + r] = kk.z;
            kv[(c4 + 3) * QK_STRIDE + r] = kk.w;
        }
        __syncthreads();

        float acc[16];
        #pragma unroll
        for (int j = 0; j < 16; j++) acc[j] = 0.f;

        #pragma unroll
        for (int d = 0; d < 64; ++d) {
            float qv = qs[qi * QK_STRIDE + d];
            const float4* kr = (const float4*)&kv[d * QK_STRIDE + kj0];
            float4 k0 = kr[0], k1 = kr[1], k2 = kr[2], k3 = kr[3];
            acc[0]  += qv * k0.x; acc[1]  += qv * k0.y; acc[2]  += qv * k0.z; acc[3]  += qv * k0.w;
            acc[4]  += qv * k1.x; acc[5]  += qv * k1.y; acc[6]  += qv * k1.z; acc[7]  += qv * k1.w;
            acc[8]  += qv * k2.x; acc[9]  += qv * k2.y; acc[10] += qv * k2.z; acc[11] += qv * k2.w;
            acc[12] += qv * k3.x; acc[13] += qv * k3.y; acc[14] += qv * k3.z; acc[15] += qv * k3.w;
        }

        const float* adjr = &adj[((size_t)(b * S_ + qg)) * S_ + kt * 64 + kj0];
        const int*   mr   = &mask[b * S_ + kt * 64 + kj0];
        float*       scr  = &sc[qi * SC_STRIDE + kt * 64 + kj0];
        #pragma unroll
        for (int j = 0; j < 16; j++)
            scr[j] = acc[j] + (float)mr[j] * -1e9f + adjr[j];
    }
    __syncthreads();

    // ---- phase 2: softmax (warp per row) ----
    {
        const int warp = t >> 5, lane = t & 31;
        for (int row = warp; row < 64; row += 8) {
            float* r = &sc[row * SC_STRIDE];
            float mx = -3.0e38f;
            #pragma unroll
            for (int i = 0; i < 16; i++) mx = fmaxf(mx, r[lane + 32 * i]);
            #pragma unroll
            for (int o = 16; o; o >>= 1) mx = fmaxf(mx, __shfl_xor_sync(0xffffffffu, mx, o));
            float e[16], sum = 0.f;
            #pragma unroll
            for (int i = 0; i < 16; i++) { e[i] = __expf(r[lane + 32 * i] - mx); sum += e[i]; }
            #pragma unroll
            for (int o = 16; o; o >>= 1) sum += __shfl_xor_sync(0xffffffffu, sum, o);
            const float inv = 1.0f / sum;
            #pragma unroll
            for (int i = 0; i < 16; i++) r[lane + 32 * i] = e[i] * inv;
        }
    }

    // ---- phase 3: ctx = P @ V ----
    const int dc0 = kj0;
    float acc[16];
    #pragma unroll
    for (int j = 0; j < 16; j++) acc[j] = 0.f;

    for (int kt = 0; kt < 8; ++kt) {
        __syncthreads();   // protect kv reuse; also orders softmax on kt==0
        #pragma unroll
        for (int i = 0; i < 4; i++) {
            int lin = t + i * 256;
            int r = lin >> 4, c4 = (lin & 15) << 2;
            float4 vv = *(const float4*)&V[(size_t)(b * S_ + kt * 64 + r) * D_ + h * DK_ + c4];
            *(float4*)&kv[r * QK_STRIDE + c4] = vv;   // row-major: kv[k][d]
        }
        __syncthreads();

        #pragma unroll
        for (int kk = 0; kk < 64; ++kk) {
            float p = sc[qi * SC_STRIDE + kt * 64 + kk];
            const float4* vr = (const float4*)&kv[kk * QK_STRIDE + dc0];
            float4 v0 = vr[0], v1 = vr[1], v2 = vr[2], v3 = vr[3];
            acc[0]  += p * v0.x; acc[1]  += p * v0.y; acc[2]  += p * v0.z; acc[3]  += p * v0.w;
            acc[4]  += p * v1.x; acc[5]  += p * v1.y; acc[6]  += p * v1.z; acc[7]  += p * v1.w;
            acc[8]  += p * v2.x; acc[9]  += p * v2.y; acc[10] += p * v2.z; acc[11] += p * v2.w;
            acc[12] += p * v3.x; acc[13] += p * v3.y; acc[14] += p * v3.z; acc[15] += p * v3.w;
        }
    }

    float* outp = &ctx[(size_t)(qbase + qi) * D_ + h * DK_ + dc0];
    *(float4*)&outp[0]  = *(float4*)&acc[0];
    *(float4*)&outp[4]  = *(float4*)&acc[4];
    *(float4*)&outp[8]  = *(float4*)&acc[8];
    *(float4*)&outp[12] = *(float4*)&acc[12];
}

// ---------------------------------------------------------------------------
// Residual + LayerNorm: out = gamma*(v-mean)/(std_unbiased + 1e-6) + beta
// v = A[row] + Bm[row]. One block (256 thr) per row of 1024.
// ---------------------------------------------------------------------------
__device__ __forceinline__ float blockReduceSum(float val, float* shared) {
    const int lane = threadIdx.x & 31, wid = threadIdx.x >> 5;
    #pragma unroll
    for (int o = 16; o; o >>= 1) val += __shfl_xor_sync(0xffffffffu, val, o);
    __syncthreads();                  // protect shared[] reuse across calls
    if (lane == 0) shared[wid] = val;
    __syncthreads();
    float r = shared[0];
    #pragma unroll
    for (int w = 1; w < 8; w++) r += shared[w];
    return r;
}

__global__ __launch_bounds__(256) void ln_residual_kernel(
    const float* __restrict__ A, const float* __restrict__ Bm,
    const float* __restrict__ gamma, const float* __restrict__ beta,
    float* __restrict__ out)
{
    __shared__ float red[8];
    const int row = blockIdx.x;
    const int tid = threadIdx.x;
    const size_t base = (size_t)row * D_;

    float v[4];
    float s = 0.f;
    #pragma unroll
    for (int i = 0; i < 4; i++) {
        int c = tid + 256 * i;
        v[i] = A[base + c] + Bm[base + c];
        s += v[i];
    }
    s = blockReduceSum(s, red);
    const float mean = s * (1.0f / (float)D_);

    float s2 = 0.f;
    #pragma unroll
    for (int i = 0; i < 4; i++) { float d = v[i] - mean; s2 += d * d; }
    s2 = blockReduceSum(s2, red);

    const float stdv = sqrtf(s2 * (1.0f / (float)(D_ - 1)));   // ddof=1
    const float inv  = 1.0f / (stdv + 1e-6f);                  // /(std+eps)

    #pragma unroll
    for (int i = 0; i < 4; i++) {
        int c = tid + 256 * i;
        out[base + c] = gamma[c] * (v[i] - mean) * inv + beta[c];
    }
}

// ---------------------------------------------------------------------------
// launch
// ---------------------------------------------------------------------------
extern "C" void kernel_launch(void* const* d_in, const int* in_sizes, int n_in,
                              void* d_out, int out_size)
{
    const float* x    = (const float*)d_in[0];
    const int*   mask = (const int*)  d_in[1];
    const float* adj  = (const float*)d_in[2];
    // d_in[3] = num_head (known: 16)
    const float* Wq = (const float*)d_in[4];  const float* bq = (const float*)d_in[5];
    const float* Wk = (const float*)d_in[6];  const float* bk = (const float*)d_in[7];
    const float* Wv = (const float*)d_in[8];  const float* bv = (const float*)d_in[9];
    const float* Wo = (const float*)d_in[10]; const float* bo = (const float*)d_in[11];
    const float* W1 = (const float*)d_in[12]; const float* b1 = (const float*)d_in[13];
    const float* W2 = (const float*)d_in[14]; const float* b2 = (const float*)d_in[15];
    const float* gamma = (const float*)d_in[16];
    const float* beta  = (const float*)d_in[17];
    float* out = (float*)d_out;

    float *q, *k, *v, *ctx, *attn, *out1, *hbuf, *ffn;
    cudaGetSymbolAddress((void**)&q,    g_q);
    cudaGetSymbolAddress((void**)&k,    g_k);
    cudaGetSymbolAddress((void**)&v,    g_v);
    cudaGetSymbolAddress((void**)&ctx,  g_ctx);
    cudaGetSymbolAddress((void**)&attn, g_attn);
    cudaGetSymbolAddress((void**)&out1, g_out1);
    cudaGetSymbolAddress((void**)&hbuf, g_h);
    cudaGetSymbolAddress((void**)&ffn,  g_ffn);

    const int ATTN_SMEM = (64 * SC_STRIDE + 2 * 64 * QK_STRIDE) * (int)sizeof(float);
    cudaFuncSetAttribute(attention_kernel,
                         cudaFuncAttributeMaxDynamicSharedMemorySize, ATTN_SMEM);

    dim3 gD(D_ / 128, M_ / 128);   // N=1024 GEMMs
    dim3 gF(F_ / 128, M_ / 128);   // N=4096 GEMM

    // QKV projections
    sgemm_bias<0><<<gD, 256>>>(x, Wq, bq, q, M_, D_, D_);
    sgemm_bias<0><<<gD, 256>>>(x, Wk, bk, k, M_, D_, D_);
    sgemm_bias<0><<<gD, 256>>>(x, Wv, bv, v, M_, D_, D_);

    // attention
    dim3 gA(S_ / 64, H_, B_);
    attention_kernel<<<gA, 256, ATTN_SMEM>>>(q, k, v, mask, adj, ctx);

    // output projection
    sgemm_bias<0><<<gD, 256>>>(ctx, Wo, bo, attn, M_, D_, D_);

    // LN1: out1 = LN(x + attn_out)
    ln_residual_kernel<<<M_, 256>>>(x, attn, gamma, beta, out1);

    // FFN
    sgemm_bias<1><<<gF, 256>>>(out1, W1, b1, hbuf, M_, F_, D_);
    sgemm_bias<0><<<gD, 256>>>(hbuf, W2, b2, ffn, M_, D_, F_);

    // LN2: out = LN(out1 + ffn)
    ln_residual_kernel<<<M_, 256>>>(out1, ffn, gamma, beta, out);
}

// round 3
// speedup vs baseline: 1.6887x; 1.6887x over previous
#include <cuda_runtime.h>
#include <cuda_bf16.h>
#include <stdint.h>
#include <math.h>

// ---------------------------------------------------------------------------
// EncoderLayer: B=32, S=512, D=1024, H=16, dk=64, F=4096
// Round 3: GEMMs -> tf32 tensor-core mma.sync (m16n8k8), fp32 accumulate.
// Attention + LN unchanged fp32.  (Round 2 failed to compile: missing stdint.h)
// ---------------------------------------------------------------------------

#define B_  32
#define S_  512
#define D_  1024
#define H_  16
#define DK_ 64
#define F_  4096
#define M_  (B_ * S_)          // 16384 rows

// -------------------- scratch (device globals; no allocs) ------------------
__device__ float g_q   [M_ * D_];
__device__ float g_k   [M_ * D_];
__device__ float g_v   [M_ * D_];
__device__ float g_ctx [M_ * D_];
__device__ float g_attn[M_ * D_];
__device__ float g_out1[M_ * D_];
__device__ float g_ffn [M_ * D_];
__device__ float g_h   [M_ * F_];

// ---------------------------------------------------------------------------
// Helpers
// ---------------------------------------------------------------------------
__device__ __forceinline__ float gelu_erf_f(float x) {
    return 0.5f * x * (1.0f + erff(x * 0.70710678118654752f));
}

__device__ __forceinline__ uint32_t f2tf32(float f) {
    uint32_t u;
    asm("cvt.rna.tf32.f32 %0, %1;" : "=r"(u) : "f"(f));
    return u;
}

__device__ __forceinline__ void mma_tf32(float c[4],
                                         uint32_t a0, uint32_t a1, uint32_t a2, uint32_t a3,
                                         uint32_t b0, uint32_t b1) {
    asm volatile(
        "mma.sync.aligned.m16n8k8.row.col.f32.tf32.tf32.f32 "
        "{%0,%1,%2,%3}, {%4,%5,%6,%7}, {%8,%9}, {%0,%1,%2,%3};\n"
        : "+f"(c[0]), "+f"(c[1]), "+f"(c[2]), "+f"(c[3])
        : "r"(a0), "r"(a1), "r"(a2), "r"(a3), "r"(b0), "r"(b1));
}

// ---------------------------------------------------------------------------
// tf32 GEMM: C[M,N] = act(A[M,K] @ Bmat[K,N] + bias[N])
// CTA 128x128, BK=16, 256 threads = 8 warps (2x4), warp tile 64x32.
// Smem staged as tf32 bits: As[k][m] (A transposed), Bs[k][n]. Stride 136
// makes fragment LDS conflict-free (bank = 8*(k&3) + group).
// ---------------------------------------------------------------------------
#define TSTR 136

template <int ACT>
__global__ __launch_bounds__(256) void tf32_gemm(
    const float* __restrict__ A, const float* __restrict__ Bm,
    const float* __restrict__ bias, float* __restrict__ C,
    int M, int N, int K)
{
    __shared__ uint32_t As[2][16][TSTR];
    __shared__ uint32_t Bs[2][16][TSTR];

    const int tid = threadIdx.x;
    const int bx = blockIdx.x, by = blockIdx.y;
    const int wid = tid >> 5, lane = tid & 31;
    const int wm = (wid >> 2) * 64;       // warp row offset in CTA tile
    const int wn = (wid & 3) * 32;        // warp col offset
    const int g  = lane >> 2;             // group id 0..7
    const int q  = lane & 3;              // thread-in-group 0..3

    // global load mapping
    const int arow = tid >> 1, acol = (tid & 1) * 8;         // A: 128 rows x 16 cols
    const int brow = tid >> 4, bcol = (tid & 15) * 8;        // B: 16 rows x 128 cols
    const float* Aptr = A + (size_t)(by * 128 + arow) * K + acol;
    const float* Bptr = Bm + (size_t)brow * N + bx * 128 + bcol;

    float acc[4][4][4];
    #pragma unroll
    for (int mi = 0; mi < 4; mi++)
        #pragma unroll
        for (int nj = 0; nj < 4; nj++)
            #pragma unroll
            for (int r = 0; r < 4; r++) acc[mi][nj][r] = 0.f;

    const int nk = K >> 4;   // BK = 16

    // ---- tile loader (global -> smem as tf32) ----
    auto load_tile = [&](int buf, int kt) {
        float4 a0 = *(const float4*)(Aptr + kt * 16);
        float4 a1 = *(const float4*)(Aptr + kt * 16 + 4);
        As[buf][acol + 0][arow] = f2tf32(a0.x);
        As[buf][acol + 1][arow] = f2tf32(a0.y);
        As[buf][acol + 2][arow] = f2tf32(a0.z);
        As[buf][acol + 3][arow] = f2tf32(a0.w);
        As[buf][acol + 4][arow] = f2tf32(a1.x);
        As[buf][acol + 5][arow] = f2tf32(a1.y);
        As[buf][acol + 6][arow] = f2tf32(a1.z);
        As[buf][acol + 7][arow] = f2tf32(a1.w);

        float4 b0 = *(const float4*)(Bptr + (size_t)(kt * 16) * N);
        float4 b1 = *(const float4*)(Bptr + (size_t)(kt * 16) * N + 4);
        uint4 u0 = make_uint4(f2tf32(b0.x), f2tf32(b0.y), f2tf32(b0.z), f2tf32(b0.w));
        uint4 u1 = make_uint4(f2tf32(b1.x), f2tf32(b1.y), f2tf32(b1.z), f2tf32(b1.w));
        *(uint4*)&Bs[buf][brow][bcol]     = u0;
        *(uint4*)&Bs[buf][brow][bcol + 4] = u1;
    };

    load_tile(0, 0);
    __syncthreads();

    for (int kt = 0; kt < nk; ++kt) {
        const int cur = kt & 1;
        if (kt + 1 < nk) load_tile(cur ^ 1, kt + 1);

        #pragma unroll
        for (int ks = 0; ks < 2; ++ks) {     // two k8 steps per BK=16
            const int k0 = ks * 8;
            uint32_t a[4][4], b[4][2];
            #pragma unroll
            for (int mi = 0; mi < 4; mi++) {
                const int m0 = wm + mi * 16 + g;
                a[mi][0] = As[cur][k0 + q    ][m0];
                a[mi][1] = As[cur][k0 + q    ][m0 + 8];
                a[mi][2] = As[cur][k0 + q + 4][m0];
                a[mi][3] = As[cur][k0 + q + 4][m0 + 8];
            }
            #pragma unroll
            for (int nj = 0; nj < 4; nj++) {
                const int n0 = wn + nj * 8 + g;
                b[nj][0] = Bs[cur][k0 + q    ][n0];
                b[nj][1] = Bs[cur][k0 + q + 4][n0];
            }
            #pragma unroll
            for (int mi = 0; mi < 4; mi++)
                #pragma unroll
                for (int nj = 0; nj < 4; nj++)
                    mma_tf32(acc[mi][nj], a[mi][0], a[mi][1], a[mi][2], a[mi][3],
                             b[nj][0], b[nj][1]);
        }
        __syncthreads();
    }

    // ---- epilogue: bias (+ GELU) + store ----
    #pragma unroll
    for (int nj = 0; nj < 4; nj++) {
        const int col = bx * 128 + wn + nj * 8 + 2 * q;
        const float2 bb = *(const float2*)&bias[col];
        #pragma unroll
        for (int mi = 0; mi < 4; mi++) {
            const int row0 = by * 128 + wm + mi * 16 + g;
            float2 o0, o1;
            o0.x = acc[mi][nj][0] + bb.x;
            o0.y = acc[mi][nj][1] + bb.y;
            o1.x = acc[mi][nj][2] + bb.x;
            o1.y = acc[mi][nj][3] + bb.y;
            if (ACT == 1) {
                o0.x = gelu_erf_f(o0.x); o0.y = gelu_erf_f(o0.y);
                o1.x = gelu_erf_f(o1.x); o1.y = gelu_erf_f(o1.y);
            }
            *(float2*)&C[(size_t)row0 * N + col]       = o0;
            *(float2*)&C[(size_t)(row0 + 8) * N + col] = o1;
        }
    }
}

// ---------------------------------------------------------------------------
// Fused attention: grid (S/64, H, B), 256 threads.  (unchanged fp32)
// ---------------------------------------------------------------------------
#define SC_STRIDE 516
#define QK_STRIDE 68

__global__ __launch_bounds__(256) void attention_kernel(
    const float* __restrict__ Q, const float* __restrict__ K,
    const float* __restrict__ V, const int* __restrict__ mask,
    const float* __restrict__ adj, float* __restrict__ ctx)
{
    extern __shared__ float smem[];
    float* sc = smem;                       // 64 * 516
    float* qs = sc + 64 * SC_STRIDE;        // 64 * 68
    float* kv = qs + 64 * QK_STRIDE;        // 64 * 68

    const int t  = threadIdx.x;
    const int qt = blockIdx.x, h = blockIdx.y, b = blockIdx.z;
    const int qbase = b * S_ + qt * 64;

    #pragma unroll
    for (int i = 0; i < 4; i++) {
        int lin = t + i * 256;
        int r = lin >> 4, c4 = (lin & 15) << 2;
        float4 qv = *(const float4*)&Q[(size_t)(qbase + r) * D_ + h * DK_ + c4];
        qv.x *= 0.125f; qv.y *= 0.125f; qv.z *= 0.125f; qv.w *= 0.125f;
        *(float4*)&qs[r * QK_STRIDE + c4] = qv;
    }

    const int qi  = t >> 2;
    const int kj0 = (t & 3) << 4;
    const int qg  = qt * 64 + qi;

    for (int kt = 0; kt < 8; ++kt) {
        __syncthreads();
        #pragma unroll
        for (int i = 0; i < 4; i++) {
            int lin = t + i * 256;
            int r = lin >> 4, c4 = (lin & 15) << 2;
            float4 kk = *(const float4*)&K[(size_t)(b * S_ + kt * 64 + r) * D_ + h * DK_ + c4];
            kv[(c4 + 0) * QK_STRIDE + r] = kk.x;
            kv[(c4 + 1) * QK_STRIDE + r] = kk.y;
            kv[(c4 + 2) * QK_STRIDE + r] = kk.z;
            kv[(c4 + 3) * QK_STRIDE + r] = kk.w;
        }
        __syncthreads();

        float acc[16];
        #pragma unroll
        for (int j = 0; j < 16; j++) acc[j] = 0.f;

        #pragma unroll
        for (int d = 0; d < 64; ++d) {
            float qv = qs[qi * QK_STRIDE + d];
            const float4* kr = (const float4*)&kv[d * QK_STRIDE + kj0];
            float4 k0 = kr[0], k1 = kr[1], k2 = kr[2], k3 = kr[3];
            acc[0]  += qv * k0.x; acc[1]  += qv * k0.y; acc[2]  += qv * k0.z; acc[3]  += qv * k0.w;
            acc[4]  += qv * k1.x; acc[5]  += qv * k1.y; acc[6]  += qv * k1.z; acc[7]  += qv * k1.w;
            acc[8]  += qv * k2.x; acc[9]  += qv * k2.y; acc[10] += qv * k2.z; acc[11] += qv * k2.w;
            acc[12] += qv * k3.x; acc[13] += qv * k3.y; acc[14] += qv * k3.z; acc[15] += qv * k3.w;
        }

        const float* adjr = &adj[((size_t)(b * S_ + qg)) * S_ + kt * 64 + kj0];
        const int*   mr   = &mask[b * S_ + kt * 64 + kj0];
        float*       scr  = &sc[qi * SC_STRIDE + kt * 64 + kj0];
        #pragma unroll
        for (int j = 0; j < 16; j++)
            scr[j] = acc[j] + (float)mr[j] * -1e9f + adjr[j];
    }
    __syncthreads();

    {
        const int warp = t >> 5, lane = t & 31;
        for (int row = warp; row < 64; row += 8) {
            float* r = &sc[row * SC_STRIDE];
            float mx = -3.0e38f;
            #pragma unroll
            for (int i = 0; i < 16; i++) mx = fmaxf(mx, r[lane + 32 * i]);
            #pragma unroll
            for (int o = 16; o; o >>= 1) mx = fmaxf(mx, __shfl_xor_sync(0xffffffffu, mx, o));
            float e[16], sum = 0.f;
            #pragma unroll
            for (int i = 0; i < 16; i++) { e[i] = __expf(r[lane + 32 * i] - mx); sum += e[i]; }
            #pragma unroll
            for (int o = 16; o; o >>= 1) sum += __shfl_xor_sync(0xffffffffu, sum, o);
            const float inv = 1.0f / sum;
            #pragma unroll
            for (int i = 0; i < 16; i++) r[lane + 32 * i] = e[i] * inv;
        }
    }

    const int dc0 = kj0;
    float acc[16];
    #pragma unroll
    for (int j = 0; j < 16; j++) acc[j] = 0.f;

    for (int kt = 0; kt < 8; ++kt) {
        __syncthreads();
        #pragma unroll
        for (int i = 0; i < 4; i++) {
            int lin = t + i * 256;
            int r = lin >> 4, c4 = (lin & 15) << 2;
            float4 vv = *(const float4*)&V[(size_t)(b * S_ + kt * 64 + r) * D_ + h * DK_ + c4];
            *(float4*)&kv[r * QK_STRIDE + c4] = vv;
        }
        __syncthreads();

        #pragma unroll
        for (int kk = 0; kk < 64; ++kk) {
            float p = sc[qi * SC_STRIDE + kt * 64 + kk];
            const float4* vr = (const float4*)&kv[kk * QK_STRIDE + dc0];
            float4 v0 = vr[0], v1 = vr[1], v2 = vr[2], v3 = vr[3];
            acc[0]  += p * v0.x; acc[1]  += p * v0.y; acc[2]  += p * v0.z; acc[3]  += p * v0.w;
            acc[4]  += p * v1.x; acc[5]  += p * v1.y; acc[6]  += p * v1.z; acc[7]  += p * v1.w;
            acc[8]  += p * v2.x; acc[9]  += p * v2.y; acc[10] += p * v2.z; acc[11] += p * v2.w;
            acc[12] += p * v3.x; acc[13] += p * v3.y; acc[14] += p * v3.z; acc[15] += p * v3.w;
        }
    }

    float* outp = &ctx[(size_t)(qbase + qi) * D_ + h * DK_ + dc0];
    *(float4*)&outp[0]  = *(float4*)&acc[0];
    *(float4*)&outp[4]  = *(float4*)&acc[4];
    *(float4*)&outp[8]  = *(float4*)&acc[8];
    *(float4*)&outp[12] = *(float4*)&acc[12];
}

// ---------------------------------------------------------------------------
// Residual + LayerNorm (unchanged)
// ---------------------------------------------------------------------------
__device__ __forceinline__ float blockReduceSum(float val, float* shared) {
    const int lane = threadIdx.x & 31, wid = threadIdx.x >> 5;
    #pragma unroll
    for (int o = 16; o; o >>= 1) val += __shfl_xor_sync(0xffffffffu, val, o);
    __syncthreads();
    if (lane == 0) shared[wid] = val;
    __syncthreads();
    float r = shared[0];
    #pragma unroll
    for (int w = 1; w < 8; w++) r += shared[w];
    return r;
}

__global__ __launch_bounds__(256) void ln_residual_kernel(
    const float* __restrict__ A, const float* __restrict__ Bm,
    const float* __restrict__ gamma, const float* __restrict__ beta,
    float* __restrict__ out)
{
    __shared__ float red[8];
    const int row = blockIdx.x;
    const int tid = threadIdx.x;
    const size_t base = (size_t)row * D_;

    float v[4];
    float s = 0.f;
    #pragma unroll
    for (int i = 0; i < 4; i++) {
        int c = tid + 256 * i;
        v[i] = A[base + c] + Bm[base + c];
        s += v[i];
    }
    s = blockReduceSum(s, red);
    const float mean = s * (1.0f / (float)D_);

    float s2 = 0.f;
    #pragma unroll
    for (int i = 0; i < 4; i++) { float d = v[i] - mean; s2 += d * d; }
    s2 = blockReduceSum(s2, red);

    const float stdv = sqrtf(s2 * (1.0f / (float)(D_ - 1)));
    const float inv  = 1.0f / (stdv + 1e-6f);

    #pragma unroll
    for (int i = 0; i < 4; i++) {
        int c = tid + 256 * i;
        out[base + c] = gamma[c] * (v[i] - mean) * inv + beta[c];
    }
}

// ---------------------------------------------------------------------------
// launch
// ---------------------------------------------------------------------------
extern "C" void kernel_launch(void* const* d_in, const int* in_sizes, int n_in,
                              void* d_out, int out_size)
{
    const float* x    = (const float*)d_in[0];
    const int*   mask = (const int*)  d_in[1];
    const float* adj  = (const float*)d_in[2];
    const float* Wq = (const float*)d_in[4];  const float* bq = (const float*)d_in[5];
    const float* Wk = (const float*)d_in[6];  const float* bk = (const float*)d_in[7];
    const float* Wv = (const float*)d_in[8];  const float* bv = (const float*)d_in[9];
    const float* Wo = (const float*)d_in[10]; const float* bo = (const float*)d_in[11];
    const float* W1 = (const float*)d_in[12]; const float* b1 = (const float*)d_in[13];
    const float* W2 = (const float*)d_in[14]; const float* b2 = (const float*)d_in[15];
    const float* gamma = (const float*)d_in[16];
    const float* beta  = (const float*)d_in[17];
    float* out = (float*)d_out;

    float *q, *k, *v, *ctx, *attn, *out1, *hbuf, *ffn;
    cudaGetSymbolAddress((void**)&q,    g_q);
    cudaGetSymbolAddress((void**)&k,    g_k);
    cudaGetSymbolAddress((void**)&v,    g_v);
    cudaGetSymbolAddress((void**)&ctx,  g_ctx);
    cudaGetSymbolAddress((void**)&attn, g_attn);
    cudaGetSymbolAddress((void**)&out1, g_out1);
    cudaGetSymbolAddress((void**)&hbuf, g_h);
    cudaGetSymbolAddress((void**)&ffn,  g_ffn);

    const int ATTN_SMEM = (64 * SC_STRIDE + 2 * 64 * QK_STRIDE) * (int)sizeof(float);
    cudaFuncSetAttribute(attention_kernel,
                         cudaFuncAttributeMaxDynamicSharedMemorySize, ATTN_SMEM);

    dim3 gD(D_ / 128, M_ / 128);   // N=1024 GEMMs
    dim3 gF(F_ / 128, M_ / 128);   // N=4096 GEMM

    // QKV projections (tf32 tensor cores)
    tf32_gemm<0><<<gD, 256>>>(x, Wq, bq, q, M_, D_, D_);
    tf32_gemm<0><<<gD, 256>>>(x, Wk, bk, k, M_, D_, D_);
    tf32_gemm<0><<<gD, 256>>>(x, Wv, bv, v, M_, D_, D_);

    // attention
    dim3 gA(S_ / 64, H_, B_);
    attention_kernel<<<gA, 256, ATTN_SMEM>>>(q, k, v, mask, adj, ctx);

    // output projection
    tf32_gemm<0><<<gD, 256>>>(ctx, Wo, bo, attn, M_, D_, D_);

    // LN1
    ln_residual_kernel<<<M_, 256>>>(x, attn, gamma, beta, out1);

    // FFN
    tf32_gemm<1><<<gF, 256>>>(out1, W1, b1, hbuf, M_, F_, D_);
    tf32_gemm<0><<<gD, 256>>>(hbuf, W2, b2, ffn, M_, D_, F_);

    // LN2
    ln_residual_kernel<<<M_, 256>>>(out1, ffn, gamma, beta, out);
}

// round 5
// speedup vs baseline: 1.8692x; 1.1069x over previous
#include <cuda_runtime.h>
#include <cuda_bf16.h>
#include <stdint.h>
#include <math.h>

// ---------------------------------------------------------------------------
// EncoderLayer: B=32, S=512, D=1024, H=16, dk=64, F=4096
// Round 5: tf32 warp-MMA GEMMs with cp.async 4-stage pipeline, raw fp32 in
// smem (HW truncates to tf32 inside HMMA). tcgen05 is unavailable: harness
// PTX target is sm_103 (no 'a'), which rejects tcgen05.* instructions.
// Attention + LN unchanged fp32.
// ---------------------------------------------------------------------------

#define B_  32
#define S_  512
#define D_  1024
#define H_  16
#define DK_ 64
#define F_  4096
#define M_  (B_ * S_)          // 16384 rows

// -------------------- scratch (device globals; no allocs) ------------------
__device__ float g_q   [M_ * D_];
__device__ float g_k   [M_ * D_];
__device__ float g_v   [M_ * D_];
__device__ float g_ctx [M_ * D_];
__device__ float g_attn[M_ * D_];
__device__ float g_out1[M_ * D_];
__device__ float g_ffn [M_ * D_];
__device__ float g_h   [M_ * F_];

// ---------------------------------------------------------------------------
// Helpers
// ---------------------------------------------------------------------------
__device__ __forceinline__ float gelu_erf_f(float x) {
    return 0.5f * x * (1.0f + erff(x * 0.70710678118654752f));
}

__device__ __forceinline__ uint32_t smem_u32(const void* p) {
    uint32_t a;
    asm("{ .reg .u64 t; cvta.to.shared.u64 t, %1; cvt.u32.u64 %0, t; }"
        : "=r"(a) : "l"(p));
    return a;
}

__device__ __forceinline__ void cp16(uint32_t s, const void* g) {
    asm volatile("cp.async.cg.shared.global [%0], [%1], 16;" :: "r"(s), "l"(g));
}
__device__ __forceinline__ void cp_commit() {
    asm volatile("cp.async.commit_group;" ::: "memory");
}
template <int N>
__device__ __forceinline__ void cp_wait() {
    asm volatile("cp.async.wait_group %0;" :: "n"(N) : "memory");
}

__device__ __forceinline__ void mma_tf32(float c[4],
                                         uint32_t a0, uint32_t a1, uint32_t a2, uint32_t a3,
                                         uint32_t b0, uint32_t b1) {
    asm volatile(
        "mma.sync.aligned.m16n8k8.row.col.f32.tf32.tf32.f32 "
        "{%0,%1,%2,%3}, {%4,%5,%6,%7}, {%8,%9}, {%0,%1,%2,%3};\n"
        : "+f"(c[0]), "+f"(c[1]), "+f"(c[2]), "+f"(c[3])
        : "r"(a0), "r"(a1), "r"(a2), "r"(a3), "r"(b0), "r"(b1));
}

// ---------------------------------------------------------------------------
// tf32 GEMM: C[M,N] = act(A[M,K] @ W[K,N] + bias[N])
// CTA 128x128, BK=16 per stage, 4 cp.async stages, 256 threads = 8 warps
// (2x4), warp tile 64x32.
// Smem (fp32 bits; HMMA truncates to tf32):
//   As[stage][128][20]  (row-major, pad to 20: frag banks (20g+q)%32 distinct)
//   Bs[stage][16][136]  (row-major, pad to 136: frag banks (8q+g)%32 distinct)
// Stage = 4736 floats = 18944 B; 4 stages = 75776 B dynamic smem.
// ---------------------------------------------------------------------------
#define ASTR 20
#define BSTR 136
#define STG_FLT (128 * ASTR + 16 * BSTR)   // 4736
#define GEMM_SMEM (4 * STG_FLT * 4)        // 75776 bytes

template <int ACT>
__global__ __launch_bounds__(256, 2) void tf32_gemm(
    const float* __restrict__ A, const float* __restrict__ W,
    const float* __restrict__ bias, float* __restrict__ C,
    int N, int K)
{
    extern __shared__ float sm[];

    const int tid = threadIdx.x;
    const int bx = blockIdx.x, by = blockIdx.y;
    const int wid = tid >> 5, lane = tid & 31;
    const int wm = (wid >> 2) * 64;       // warp row offset
    const int wn = (wid & 3) * 32;        // warp col offset
    const int g  = lane >> 2;             // 0..7
    const int q  = lane & 3;              // 0..3

    // global->smem load mapping (two 16B per array per thread per stage)
    const int ar = tid >> 1, ak = (tid & 1) * 8;      // A: 128 rows x 16 cols
    const int bk = tid >> 4, bn = (tid & 15) * 8;     // B: 16 rows x 128 cols
    const float* Ag = A + (size_t)(by * 128 + ar) * K + ak;
    const float* Bg = W + (size_t)bk * N + bx * 128 + bn;

    // per-stage smem byte addresses for this thread's cp.async targets
    uint32_t sA0 = smem_u32(sm) + (uint32_t)(ar * ASTR + ak) * 4u;
    uint32_t sB0 = smem_u32(sm) + (uint32_t)(128 * ASTR + bk * BSTR + bn) * 4u;

    auto issue = [&](int kt) {
        const uint32_t so = (uint32_t)(kt & 3) * (STG_FLT * 4u);
        const float* ap = Ag + kt * 16;
        const float* bp = Bg + (size_t)(kt * 16) * N;
        cp16(sA0 + so,      ap);
        cp16(sA0 + so + 16, ap + 4);
        cp16(sB0 + so,      bp);
        cp16(sB0 + so + 16, bp + 4);
        cp_commit();
    };

    float acc[4][4][4];
    #pragma unroll
    for (int mi = 0; mi < 4; mi++)
        #pragma unroll
        for (int nj = 0; nj < 4; nj++)
            #pragma unroll
            for (int r = 0; r < 4; r++) acc[mi][nj][r] = 0.f;

    const int nk = K >> 4;   // BK = 16; nk >= 64 always here

    issue(0); issue(1); issue(2);

    for (int kt = 0; kt < nk; ++kt) {
        cp_wait<2>();          // stage kt resident
        __syncthreads();       // all threads' cp.async data visible to all
        if (kt + 3 < nk) issue(kt + 3);

        const uint32_t* As32 = (const uint32_t*)(sm + (kt & 3) * STG_FLT);
        const uint32_t* Bs32 = As32 + 128 * ASTR;

        #pragma unroll
        for (int ks = 0; ks < 2; ++ks) {
            const int k0 = ks * 8;
            uint32_t a[4][4], b[4][2];
            #pragma unroll
            for (int mi = 0; mi < 4; mi++) {
                const int m0 = wm + mi * 16 + g;
                a[mi][0] = As32[(m0    ) * ASTR + k0 + q];
                a[mi][1] = As32[(m0 + 8) * ASTR + k0 + q];
                a[mi][2] = As32[(m0    ) * ASTR + k0 + q + 4];
                a[mi][3] = As32[(m0 + 8) * ASTR + k0 + q + 4];
            }
            #pragma unroll
            for (int nj = 0; nj < 4; nj++) {
                const int n0 = wn + nj * 8 + g;
                b[nj][0] = Bs32[(k0 + q    ) * BSTR + n0];
                b[nj][1] = Bs32[(k0 + q + 4) * BSTR + n0];
            }
            #pragma unroll
            for (int mi = 0; mi < 4; mi++)
                #pragma unroll
                for (int nj = 0; nj < 4; nj++)
                    mma_tf32(acc[mi][nj], a[mi][0], a[mi][1], a[mi][2], a[mi][3],
                             b[nj][0], b[nj][1]);
        }
        // no trailing sync needed: next iter's wait+sync gates buffer reuse
    }

    // ---- epilogue: bias (+ GELU) + store (proven round-3 mapping) ----
    #pragma unroll
    for (int nj = 0; nj < 4; nj++) {
        const int col = bx * 128 + wn + nj * 8 + 2 * q;
        const float2 bb = *(const float2*)&bias[col];
        #pragma unroll
        for (int mi = 0; mi < 4; mi++) {
            const int row0 = by * 128 + wm + mi * 16 + g;
            float2 o0, o1;
            o0.x = acc[mi][nj][0] + bb.x;
            o0.y = acc[mi][nj][1] + bb.y;
            o1.x = acc[mi][nj][2] + bb.x;
            o1.y = acc[mi][nj][3] + bb.y;
            if (ACT == 1) {
                o0.x = gelu_erf_f(o0.x); o0.y = gelu_erf_f(o0.y);
                o1.x = gelu_erf_f(o1.x); o1.y = gelu_erf_f(o1.y);
            }
            *(float2*)&C[(size_t)row0 * N + col]       = o0;
            *(float2*)&C[(size_t)(row0 + 8) * N + col] = o1;
        }
    }
}

// ---------------------------------------------------------------------------
// Fused attention: grid (S/64, H, B), 256 threads.  (unchanged fp32)
// ---------------------------------------------------------------------------
#define SC_STRIDE 516
#define QK_STRIDE 68

__global__ __launch_bounds__(256) void attention_kernel(
    const float* __restrict__ Q, const float* __restrict__ K,
    const float* __restrict__ V, const int* __restrict__ mask,
    const float* __restrict__ adj, float* __restrict__ ctx)
{
    extern __shared__ float smem[];
    float* sc = smem;                       // 64 * 516
    float* qs = sc + 64 * SC_STRIDE;        // 64 * 68
    float* kv = qs + 64 * QK_STRIDE;        // 64 * 68

    const int t  = threadIdx.x;
    const int qt = blockIdx.x, h = blockIdx.y, b = blockIdx.z;
    const int qbase = b * S_ + qt * 64;

    #pragma unroll
    for (int i = 0; i < 4; i++) {
        int lin = t + i * 256;
        int r = lin >> 4, c4 = (lin & 15) << 2;
        float4 qv = *(const float4*)&Q[(size_t)(qbase + r) * D_ + h * DK_ + c4];
        qv.x *= 0.125f; qv.y *= 0.125f; qv.z *= 0.125f; qv.w *= 0.125f;
        *(float4*)&qs[r * QK_STRIDE + c4] = qv;
    }

    const int qi  = t >> 2;
    const int kj0 = (t & 3) << 4;
    const int qg  = qt * 64 + qi;

    for (int kt = 0; kt < 8; ++kt) {
        __syncthreads();
        #pragma unroll
        for (int i = 0; i < 4; i++) {
            int lin = t + i * 256;
            int r = lin >> 4, c4 = (lin & 15) << 2;
            float4 kk = *(const float4*)&K[(size_t)(b * S_ + kt * 64 + r) * D_ + h * DK_ + c4];
            kv[(c4 + 0) * QK_STRIDE + r] = kk.x;
            kv[(c4 + 1) * QK_STRIDE + r] = kk.y;
            kv[(c4 + 2) * QK_STRIDE + r] = kk.z;
            kv[(c4 + 3) * QK_STRIDE + r] = kk.w;
        }
        __syncthreads();

        float acc[16];
        #pragma unroll
        for (int j = 0; j < 16; j++) acc[j] = 0.f;

        #pragma unroll
        for (int d = 0; d < 64; ++d) {
            float qv = qs[qi * QK_STRIDE + d];
            const float4* kr = (const float4*)&kv[d * QK_STRIDE + kj0];
            float4 k0 = kr[0], k1 = kr[1], k2 = kr[2], k3 = kr[3];
            acc[0]  += qv * k0.x; acc[1]  += qv * k0.y; acc[2]  += qv * k0.z; acc[3]  += qv * k0.w;
            acc[4]  += qv * k1.x; acc[5]  += qv * k1.y; acc[6]  += qv * k1.z; acc[7]  += qv * k1.w;
            acc[8]  += qv * k2.x; acc[9]  += qv * k2.y; acc[10] += qv * k2.z; acc[11] += qv * k2.w;
            acc[12] += qv * k3.x; acc[13] += qv * k3.y; acc[14] += qv * k3.z; acc[15] += qv * k3.w;
        }

        const float* adjr = &adj[((size_t)(b * S_ + qg)) * S_ + kt * 64 + kj0];
        const int*   mr   = &mask[b * S_ + kt * 64 + kj0];
        float*       scr  = &sc[qi * SC_STRIDE + kt * 64 + kj0];
        #pragma unroll
        for (int j = 0; j < 16; j++)
            scr[j] = acc[j] + (float)mr[j] * -1e9f + adjr[j];
    }
    __syncthreads();

    {
        const int warp = t >> 5, lane = t & 31;
        for (int row = warp; row < 64; row += 8) {
            float* r = &sc[row * SC_STRIDE];
            float mx = -3.0e38f;
            #pragma unroll
            for (int i = 0; i < 16; i++) mx = fmaxf(mx, r[lane + 32 * i]);
            #pragma unroll
            for (int o = 16; o; o >>= 1) mx = fmaxf(mx, __shfl_xor_sync(0xffffffffu, mx, o));
            float e[16], sum = 0.f;
            #pragma unroll
            for (int i = 0; i < 16; i++) { e[i] = __expf(r[lane + 32 * i] - mx); sum += e[i]; }
            #pragma unroll
            for (int o = 16; o; o >>= 1) sum += __shfl_xor_sync(0xffffffffu, sum, o);
            const float inv = 1.0f / sum;
            #pragma unroll
            for (int i = 0; i < 16; i++) r[lane + 32 * i] = e[i] * inv;
        }
    }

    const int dc0 = kj0;
    float acc[16];
    #pragma unroll
    for (int j = 0; j < 16; j++) acc[j] = 0.f;

    for (int kt = 0; kt < 8; ++kt) {
        __syncthreads();
        #pragma unroll
        for (int i = 0; i < 4; i++) {
            int lin = t + i * 256;
            int r = lin >> 4, c4 = (lin & 15) << 2;
            float4 vv = *(const float4*)&V[(size_t)(b * S_ + kt * 64 + r) * D_ + h * DK_ + c4];
            *(float4*)&kv[r * QK_STRIDE + c4] = vv;
        }
        __syncthreads();

        #pragma unroll
        for (int kk = 0; kk < 64; ++kk) {
            float p = sc[qi * SC_STRIDE + kt * 64 + kk];
            const float4* vr = (const float4*)&kv[kk * QK_STRIDE + dc0];
            float4 v0 = vr[0], v1 = vr[1], v2 = vr[2], v3 = vr[3];
            acc[0]  += p * v0.x; acc[1]  += p * v0.y; acc[2]  += p * v0.z; acc[3]  += p * v0.w;
            acc[4]  += p * v1.x; acc[5]  += p * v1.y; acc[6]  += p * v1.z; acc[7]  += p * v1.w;
            acc[8]  += p * v2.x; acc[9]  += p * v2.y; acc[10] += p * v2.z; acc[11] += p * v2.w;
            acc[12] += p * v3.x; acc[13] += p * v3.y; acc[14] += p * v3.z; acc[15] += p * v3.w;
        }
    }

    float* outp = &ctx[(size_t)(qbase + qi) * D_ + h * DK_ + dc0];
    *(float4*)&outp[0]  = *(float4*)&acc[0];
    *(float4*)&outp[4]  = *(float4*)&acc[4];
    *(float4*)&outp[8]  = *(float4*)&acc[8];
    *(float4*)&outp[12] = *(float4*)&acc[12];
}

// ---------------------------------------------------------------------------
// Residual + LayerNorm (unchanged)
// ---------------------------------------------------------------------------
__device__ __forceinline__ float blockReduceSum(float val, float* shared) {
    const int lane = threadIdx.x & 31, wid = threadIdx.x >> 5;
    #pragma unroll
    for (int o = 16; o; o >>= 1) val += __shfl_xor_sync(0xffffffffu, val, o);
    __syncthreads();
    if (lane == 0) shared[wid] = val;
    __syncthreads();
    float r = shared[0];
    #pragma unroll
    for (int w = 1; w < 8; w++) r += shared[w];
    return r;
}

__global__ __launch_bounds__(256) void ln_residual_kernel(
    const float* __restrict__ A, const float* __restrict__ Bm,
    const float* __restrict__ gamma, const float* __restrict__ beta,
    float* __restrict__ out)
{
    __shared__ float red[8];
    const int row = blockIdx.x;
    const int tid = threadIdx.x;
    const size_t base = (size_t)row * D_;

    float v[4];
    float s = 0.f;
    #pragma unroll
    for (int i = 0; i < 4; i++) {
        int c = tid + 256 * i;
        v[i] = A[base + c] + Bm[base + c];
        s += v[i];
    }
    s = blockReduceSum(s, red);
    const float mean = s * (1.0f / (float)D_);

    float s2 = 0.f;
    #pragma unroll
    for (int i = 0; i < 4; i++) { float d = v[i] - mean; s2 += d * d; }
    s2 = blockReduceSum(s2, red);

    const float stdv = sqrtf(s2 * (1.0f / (float)(D_ - 1)));
    const float inv  = 1.0f / (stdv + 1e-6f);

    #pragma unroll
    for (int i = 0; i < 4; i++) {
        int c = tid + 256 * i;
        out[base + c] = gamma[c] * (v[i] - mean) * inv + beta[c];
    }
}

// ---------------------------------------------------------------------------
// launch
// ---------------------------------------------------------------------------
extern "C" void kernel_launch(void* const* d_in, const int* in_sizes, int n_in,
                              void* d_out, int out_size)
{
    const float* x    = (const float*)d_in[0];
    const int*   mask = (const int*)  d_in[1];
    const float* adj  = (const float*)d_in[2];
    const float* Wq = (const float*)d_in[4];  const float* bq = (const float*)d_in[5];
    const float* Wk = (const float*)d_in[6];  const float* bk = (const float*)d_in[7];
    const float* Wv = (const float*)d_in[8];  const float* bv = (const float*)d_in[9];
    const float* Wo = (const float*)d_in[10]; const float* bo = (const float*)d_in[11];
    const float* W1 = (const float*)d_in[12]; const float* b1 = (const float*)d_in[13];
    const float* W2 = (const float*)d_in[14]; const float* b2 = (const float*)d_in[15];
    const float* gamma = (const float*)d_in[16];
    const float* beta  = (const float*)d_in[17];
    float* out = (float*)d_out;

    float *q, *k, *v, *ctx, *attn, *out1, *hbuf, *ffn;
    cudaGetSymbolAddress((void**)&q,    g_q);
    cudaGetSymbolAddress((void**)&k,    g_k);
    cudaGetSymbolAddress((void**)&v,    g_v);
    cudaGetSymbolAddress((void**)&ctx,  g_ctx);
    cudaGetSymbolAddress((void**)&attn, g_attn);
    cudaGetSymbolAddress((void**)&out1, g_out1);
    cudaGetSymbolAddress((void**)&hbuf, g_h);
    cudaGetSymbolAddress((void**)&ffn,  g_ffn);

    cudaFuncSetAttribute(tf32_gemm<0>,
                         cudaFuncAttributeMaxDynamicSharedMemorySize, GEMM_SMEM);
    cudaFuncSetAttribute(tf32_gemm<1>,
                         cudaFuncAttributeMaxDynamicSharedMemorySize, GEMM_SMEM);

    const int ATTN_SMEM = (64 * SC_STRIDE + 2 * 64 * QK_STRIDE) * (int)sizeof(float);
    cudaFuncSetAttribute(attention_kernel,
                         cudaFuncAttributeMaxDynamicSharedMemorySize, ATTN_SMEM);

    dim3 gD(D_ / 128, M_ / 128);   // (8, 128)
    dim3 gF(F_ / 128, M_ / 128);   // (32, 128)

    // QKV projections
    tf32_gemm<0><<<gD, 256, GEMM_SMEM>>>(x, Wq, bq, q, D_, D_);
    tf32_gemm<0><<<gD, 256, GEMM_SMEM>>>(x, Wk, bk, k, D_, D_);
    tf32_gemm<0><<<gD, 256, GEMM_SMEM>>>(x, Wv, bv, v, D_, D_);

    // attention
    dim3 gA(S_ / 64, H_, B_);
    attention_kernel<<<gA, 256, ATTN_SMEM>>>(q, k, v, mask, adj, ctx);

    // output projection
    tf32_gemm<0><<<gD, 256, GEMM_SMEM>>>(ctx, Wo, bo, attn, D_, D_);

    // LN1
    ln_residual_kernel<<<M_, 256>>>(x, attn, gamma, beta, out1);

    // FFN
    tf32_gemm<1><<<gF, 256, GEMM_SMEM>>>(out1, W1, b1, hbuf, F_, D_);
    tf32_gemm<0><<<gD, 256, GEMM_SMEM>>>(hbuf, W2, b2, ffn, D_, F_);

    // LN2
    ln_residual_kernel<<<M_, 256>>>(out1, ffn, gamma, beta, out);
}